// round 14
// baseline (speedup 1.0000x reference)
#include <cuda_runtime.h>
#include <cuda_fp16.h>
#include <cstdint>

// B=2,H=16,S=2048,D=64 causal attention, fp32 in/out.
#define BHN   32
#define SEQ   2048
#define DH    64
#define BM    64                        // q rows per CTA (4 warps x 16)
#define BN    64
#define NTHR  128
#define NELEM (BHN * SEQ * DH)          // 4,194,304

#define QSCALE 0.18033688f              // 0.125 * log2(e)
#define ONESH2 0x3C003C00u              // fp16x2 {1.0, 1.0}

// ---- pre-converted fp16 operands ----
__device__ __align__(16) uint8_t gKhi[NELEM * 2];
__device__ __align__(16) uint8_t gVhi[NELEM * 2];

// ---- smem: 3 stages x 16KB (KHI|VHI, 8KB each, XOR-swizzled) ----
#define STAGE   16384
#define P_KHI   0
#define P_VHI   8192
#define SMEM_BYTES (3 * STAGE)          // 49152 -> 4 CTAs/SM (192KB)

__device__ __forceinline__ uint32_t smem_u32(const void* p) {
    uint32_t a;
    asm("{ .reg .u64 t; cvta.to.shared.u64 t, %1; cvt.u32.u64 %0, t; }" : "=r"(a) : "l"(p));
    return a;
}
__device__ __forceinline__ uint32_t swz(uint32_t b) { return b ^ ((b >> 3) & 0x70u); }
__device__ __forceinline__ float ex2(float x) {
    float r; asm("ex2.approx.f32 %0, %1;" : "=f"(r) : "f"(x)); return r;
}
__device__ __forceinline__ uint32_t ex2h2(uint32_t x) {
    uint32_t r; asm("ex2.approx.f16x2 %0, %1;" : "=r"(r) : "r"(x)); return r;
}
__device__ __forceinline__ void cpa16(uint32_t dst, const void* src) {
    asm volatile("cp.async.cg.shared.global [%0], [%1], 16;" :: "r"(dst), "l"(src));
}
#define CP_COMMIT() asm volatile("cp.async.commit_group;" ::: "memory")
#define CP_WAIT(n)  asm volatile("cp.async.wait_group %0;" :: "n"(n) : "memory")

__device__ __forceinline__ void ldsm4(uint32_t r[4], uint32_t addr) {
    asm volatile("ldmatrix.sync.aligned.m8n8.x4.shared.b16 {%0,%1,%2,%3}, [%4];"
        : "=r"(r[0]), "=r"(r[1]), "=r"(r[2]), "=r"(r[3]) : "r"(addr));
}
__device__ __forceinline__ void ldsm4t(uint32_t r[4], uint32_t addr) {
    asm volatile("ldmatrix.sync.aligned.m8n8.x4.trans.shared.b16 {%0,%1,%2,%3}, [%4];"
        : "=r"(r[0]), "=r"(r[1]), "=r"(r[2]), "=r"(r[3]) : "r"(addr));
}
// not volatile: lets ptxas schedule HMMA around FMA/MUFU chains
__device__ __forceinline__ void mma_f16(float c[4], const uint32_t a[4],
                                        uint32_t b0, uint32_t b1) {
    asm("mma.sync.aligned.m16n8k16.row.col.f32.f16.f16.f32 "
        "{%0,%1,%2,%3}, {%4,%5,%6,%7}, {%8,%9}, {%0,%1,%2,%3};"
        : "+f"(c[0]), "+f"(c[1]), "+f"(c[2]), "+f"(c[3])
        : "r"(a[0]), "r"(a[1]), "r"(a[2]), "r"(a[3]), "r"(b0), "r"(b1));
}
__device__ __forceinline__ uint32_t packh(float lo, float hi) {
    uint32_t r;
    asm("cvt.rn.f16x2.f32 %0, %1, %2;" : "=r"(r) : "f"(hi), "f"(lo));
    return r;
}

// ================= pre-pass: K,V fp32 -> fp16 =================
__global__ __launch_bounds__(256)
void prep_kernel(const float* __restrict__ Kg, const float* __restrict__ Vg)
{
    const int i = blockIdx.x * 256 + threadIdx.x;      // per float4
    const int t = blockIdx.y;                          // 0=K 1=V
    const float4* src = (t == 0) ? (const float4*)Kg : (const float4*)Vg;
    uint2* hi = (t == 0) ? (uint2*)gKhi : (uint2*)gVhi;

    float4 v = src[i];
    uint2 h;
    h.x = packh(v.x, v.y);
    h.y = packh(v.z, v.w);
    hi[i] = h;
}

// ================= main attention kernel =================
__global__ __launch_bounds__(NTHR, 4)
void fattn_mma_kernel(float* __restrict__ Og, const float* __restrict__ Qg)
{
    extern __shared__ __align__(1024) uint8_t smem[];
    const uint32_t sb = smem_u32(smem);

    const int tid  = threadIdx.x;
    const int w    = tid >> 5;           // 0..3
    const int lane = tid & 31;
    const int lr   = lane & 15;
    const int lc   = (lane >> 4) << 3;
    const int quad = lane & 3;

    const int qt = (gridDim.x - 1) - blockIdx.x;   // heavy tiles first
    const int bh = blockIdx.y;
    const size_t rowbase = (size_t)bh * SEQ;       // 128B-row index base

    const int n_kv = qt + 1;                       // kv tiles 0..qt (BM == BN)

    // hoisted swizzled address components:
    // swz(row*128 + col) == row*128 + (col ^ ((lr&7)<<4))  for col in [0,128)
    const uint32_t xorp = (uint32_t)((lr & 7) << 4);
    uint32_t rowoff[4], coloff[4];
    #pragma unroll
    for (int g = 0; g < 4; g++) {
        rowoff[g] = (uint32_t)((g * 16 + lr) * 128);
        coloff[g] = ((uint32_t)(g * 32 + lc * 2)) ^ xorp;
    }

    // tile issuer: one 16KB stage (KHI|VHI); 8 cp.async per thread
    auto issue_tile = [&](int kt, uint32_t stg) {
        const size_t tb = (rowbase + (size_t)kt * BN) * 128;
        const uint8_t* kh = gKhi + tb;
        const uint8_t* vh = gVhi + tb;
        #pragma unroll
        for (int j = 0; j < 4; j++) {
            uint32_t idx = (uint32_t)(tid + j * NTHR);
            uint32_t off = idx << 4;                 // 0..8176
            uint32_t so  = sb + stg + swz(off);
            cpa16(so + P_KHI, kh + off);
            cpa16(so + P_VHI, vh + off);
        }
        CP_COMMIT();
    };

    issue_tile(0, 0);                   // tile 0 -> stage 0

    // ---- Q: load fp32, scale, fp16 pack, stage in stage-2 region (8KB) ----
    // Stage 2 is first overwritten by issue(tile 2) at iter 0, after BAR(0) —
    // all warps have extracted their Q fragments by then.
    {
        const float* Qb = Qg + (rowbase + (size_t)qt * BM) * DH;
        #pragma unroll
        for (int it = 0; it < 8; it++) {
            int i  = tid + it * NTHR;   // 0..1023 float4
            int r  = i >> 4;
            int c4 = (i & 15) << 2;
            float4 v = *(const float4*)(Qb + r * DH + c4);
            uint2 h;
            h.x = packh(v.x * QSCALE, v.y * QSCALE);
            h.y = packh(v.z * QSCALE, v.w * QSCALE);
            *(uint2*)(smem + 2 * STAGE + swz((uint32_t)(r * 128 + c4 * 2))) = h;
        }
    }
    __syncthreads();

    uint32_t qh[4][4];
    #pragma unroll
    for (int ks = 0; ks < 4; ks++)
        ldsm4(qh[ks], sb + 2 * STAGE + rowoff[w] + coloff[ks]);

    // pre-issue tile 1 into stage 1
    if (qt >= 1) issue_tile(1, STAGE);

    float o[8][4];
    #pragma unroll
    for (int n = 0; n < 8; n++)
        #pragma unroll
        for (int j = 0; j < 4; j++) o[n][j] = 0.f;
    float ol[4] = {0.f, 0.f, 0.f, 0.f};  // ones-column accum: row sums of P
    float m0 = -1e30f, m1 = -1e30f;

    const int qg0 = qt * BM + w * 16 + (lane >> 2);

    for (int kt = 0; kt < n_kv; kt++) {
        // pending-newer-than-kt = min(qt-kt, 1)
        if (kt < qt) { CP_WAIT(1); } else { CP_WAIT(0); }
        __syncthreads();                 // single barrier: publish + WAR guard
        if (kt + 2 <= qt) issue_tile(kt + 2, (uint32_t)((kt + 2) % 3) * STAGE);

        const uint32_t stg = sb + (uint32_t)(kt % 3) * STAGE;

        // ---- S = Q.Khi  (single-pass fp16) ----
        float s[8][4];
        #pragma unroll
        for (int n = 0; n < 8; n++)
            #pragma unroll
            for (int j = 0; j < 4; j++) s[n][j] = 0.f;

        #pragma unroll
        for (int ks = 0; ks < 4; ks++) {
            #pragma unroll
            for (int kg = 0; kg < 4; kg++) {
                uint32_t bhf[4];
                ldsm4(bhf, stg + P_KHI + rowoff[kg] + coloff[ks]);
                mma_f16(s[2*kg],   qh[ks], bhf[0], bhf[2]);
                mma_f16(s[2*kg+1], qh[ks], bhf[1], bhf[3]);
            }
        }

        // ---- causal mask (diagonal tile only) ----
        if (kt == qt) {
            #pragma unroll
            for (int n = 0; n < 8; n++) {
                int kb = kt * BN + n * 8 + quad * 2;
                if (kb     > qg0)     s[n][0] = -30000.f;
                if (kb + 1 > qg0)     s[n][1] = -30000.f;
                if (kb     > qg0 + 8) s[n][2] = -30000.f;
                if (kb + 1 > qg0 + 8) s[n][3] = -30000.f;
            }
        }

        // ---- online softmax (log2 domain), l folded into PV via ones column ----
        float mx0 = s[0][0], mx1 = s[0][2];
        #pragma unroll
        for (int n = 0; n < 8; n++) {
            mx0 = fmaxf(mx0, fmaxf(s[n][0], s[n][1]));
            mx1 = fmaxf(mx1, fmaxf(s[n][2], s[n][3]));
        }
        mx0 = fmaxf(mx0, __shfl_xor_sync(0xffffffffu, mx0, 1));
        mx0 = fmaxf(mx0, __shfl_xor_sync(0xffffffffu, mx0, 2));
        mx1 = fmaxf(mx1, __shfl_xor_sync(0xffffffffu, mx1, 1));
        mx1 = fmaxf(mx1, __shfl_xor_sync(0xffffffffu, mx1, 2));

        if (__any_sync(0xffffffffu, (mx0 > m0) || (mx1 > m1))) {
            float mn0 = fmaxf(m0, mx0), mn1 = fmaxf(m1, mx1);
            float a0 = ex2(m0 - mn0), a1 = ex2(m1 - mn1);
            m0 = mn0; m1 = mn1;
            #pragma unroll
            for (int n = 0; n < 8; n++) {
                o[n][0] *= a0; o[n][1] *= a0;
                o[n][2] *= a1; o[n][3] *= a1;
            }
            ol[0] *= a0; ol[1] *= a0;
            ol[2] *= a1; ol[3] *= a1;
        }

        // ---- P = exp2(s - m) computed directly in fp16x2 A-fragments ----
        uint32_t pa[4][4];
        #pragma unroll
        for (int j = 0; j < 4; j++) {
            pa[j][0] = ex2h2(packh(s[2*j][0]   - m0, s[2*j][1]   - m0));
            pa[j][1] = ex2h2(packh(s[2*j][2]   - m1, s[2*j][3]   - m1));
            pa[j][2] = ex2h2(packh(s[2*j+1][0] - m0, s[2*j+1][1] - m0));
            pa[j][3] = ex2h2(packh(s[2*j+1][2] - m1, s[2*j+1][3] - m1));
        }

        // ---- ol += P.1 first (no ldsm dependency -> tensor starts at once),
        //      then O += P.Vhi ----
        #pragma unroll
        for (int ks = 0; ks < 4; ks++) {
            mma_f16(ol, pa[ks], ONESH2, ONESH2);
            #pragma unroll
            for (int dg = 0; dg < 4; dg++) {
                uint32_t vhf[4];
                ldsm4t(vhf, stg + P_VHI + rowoff[ks] + coloff[dg]);
                mma_f16(o[2*dg],   pa[ks], vhf[0], vhf[1]);
                mma_f16(o[2*dg+1], pa[ks], vhf[2], vhf[3]);
            }
        }
    }

    // ---- epilogue: normalize by ones-column sums ----
    float inv0 = 1.0f / ol[0], inv1 = 1.0f / ol[2];
    float* Orow0 = Og + (rowbase + qg0) * DH;
    float* Orow1 = Orow0 + 8 * DH;
    #pragma unroll
    for (int n = 0; n < 8; n++) {
        int d = n * 8 + quad * 2;
        *(float2*)(Orow0 + d) = make_float2(o[n][0] * inv0, o[n][1] * inv0);
        *(float2*)(Orow1 + d) = make_float2(o[n][2] * inv1, o[n][3] * inv1);
    }
}

extern "C" void kernel_launch(void* const* d_in, const int* in_sizes, int n_in,
                              void* d_out, int out_size)
{
    const float* Q = (const float*)d_in[0];
    const float* K = (const float*)d_in[1];
    const float* V = (const float*)d_in[2];
    float* O = (float*)d_out;

    dim3 pgrid(NELEM / 4 / 256, 2);     // (4096, 2): K and V
    prep_kernel<<<pgrid, 256>>>(K, V);

    cudaFuncSetAttribute(fattn_mma_kernel,
                         cudaFuncAttributeMaxDynamicSharedMemorySize, SMEM_BYTES);
    dim3 grid(SEQ / BM, BHN);           // (32, 32)
    fattn_mma_kernel<<<grid, NTHR, SMEM_BYTES>>>(O, Q);
}

// round 15
// speedup vs baseline: 1.0199x; 1.0199x over previous
#include <cuda_runtime.h>
#include <cuda_fp16.h>
#include <cstdint>

// B=2,H=16,S=2048,D=64 causal attention, fp32 in/out.
#define BHN   32
#define SEQ   2048
#define DH    64
#define BM    64                        // q rows per CTA (4 warps x 16)
#define BN    64
#define NTHR  128
#define NELEM (BHN * SEQ * DH)          // 4,194,304

#define QSCALE 0.18033688f              // 0.125 * log2(e)
#define ONESH2 0x3C003C00u              // fp16x2 {1.0, 1.0}

// ---- pre-converted fp16 operands ----
__device__ __align__(16) uint8_t gKhi[NELEM * 2];
__device__ __align__(16) uint8_t gVhi[NELEM * 2];

// ---- smem: 4 stages x 16KB (KHI|VHI, 8KB each, XOR-swizzled) ----
#define STAGE   16384
#define P_KHI   0
#define P_VHI   8192
#define SMEM_BYTES (4 * STAGE)          // 65536 -> 3 CTAs/SM (192KB)

__device__ __forceinline__ uint32_t smem_u32(const void* p) {
    uint32_t a;
    asm("{ .reg .u64 t; cvta.to.shared.u64 t, %1; cvt.u32.u64 %0, t; }" : "=r"(a) : "l"(p));
    return a;
}
__device__ __forceinline__ uint32_t swz(uint32_t b) { return b ^ ((b >> 3) & 0x70u); }
__device__ __forceinline__ float ex2(float x) {
    float r; asm("ex2.approx.f32 %0, %1;" : "=f"(r) : "f"(x)); return r;
}
__device__ __forceinline__ uint32_t ex2h2(uint32_t x) {
    uint32_t r; asm("ex2.approx.f16x2 %0, %1;" : "=r"(r) : "r"(x)); return r;
}
__device__ __forceinline__ uint32_t maxh2(uint32_t a, uint32_t b) {
    uint32_t r; asm("max.f16x2 %0, %1, %2;" : "=r"(r) : "r"(a), "r"(b)); return r;
}
__device__ __forceinline__ float h2lo_f32(uint32_t h) {
    float r; asm("{ .reg .b16 x, y; mov.b32 {x, y}, %1; cvt.f32.f16 %0, x; }"
                 : "=f"(r) : "r"(h));
    return r;
}
__device__ __forceinline__ float h2hi_f32(uint32_t h) {
    float r; asm("{ .reg .b16 x, y; mov.b32 {x, y}, %1; cvt.f32.f16 %0, y; }"
                 : "=f"(r) : "r"(h));
    return r;
}
__device__ __forceinline__ void cpa16(uint32_t dst, const void* src) {
    asm volatile("cp.async.cg.shared.global [%0], [%1], 16;" :: "r"(dst), "l"(src));
}
#define CP_COMMIT() asm volatile("cp.async.commit_group;" ::: "memory")
#define CP_WAIT(n)  asm volatile("cp.async.wait_group %0;" :: "n"(n) : "memory")

__device__ __forceinline__ void ldsm4(uint32_t r[4], uint32_t addr) {
    asm volatile("ldmatrix.sync.aligned.m8n8.x4.shared.b16 {%0,%1,%2,%3}, [%4];"
        : "=r"(r[0]), "=r"(r[1]), "=r"(r[2]), "=r"(r[3]) : "r"(addr));
}
__device__ __forceinline__ void ldsm4t(uint32_t r[4], uint32_t addr) {
    asm volatile("ldmatrix.sync.aligned.m8n8.x4.trans.shared.b16 {%0,%1,%2,%3}, [%4];"
        : "=r"(r[0]), "=r"(r[1]), "=r"(r[2]), "=r"(r[3]) : "r"(addr));
}
// not volatile: lets ptxas schedule HMMA around FMA/MUFU chains
__device__ __forceinline__ void mma_f16(float c[4], const uint32_t a[4],
                                        uint32_t b0, uint32_t b1) {
    asm("mma.sync.aligned.m16n8k16.row.col.f32.f16.f16.f32 "
        "{%0,%1,%2,%3}, {%4,%5,%6,%7}, {%8,%9}, {%0,%1,%2,%3};"
        : "+f"(c[0]), "+f"(c[1]), "+f"(c[2]), "+f"(c[3])
        : "r"(a[0]), "r"(a[1]), "r"(a[2]), "r"(a[3]), "r"(b0), "r"(b1));
}
__device__ __forceinline__ uint32_t packh(float lo, float hi) {
    uint32_t r;
    asm("cvt.rn.f16x2.f32 %0, %1, %2;" : "=r"(r) : "f"(hi), "f"(lo));
    return r;
}

// ================= pre-pass: K,V fp32 -> fp16 =================
__global__ __launch_bounds__(256)
void prep_kernel(const float* __restrict__ Kg, const float* __restrict__ Vg)
{
    const int i = blockIdx.x * 256 + threadIdx.x;      // per float4
    const int t = blockIdx.y;                          // 0=K 1=V
    const float4* src = (t == 0) ? (const float4*)Kg : (const float4*)Vg;
    uint2* hi = (t == 0) ? (uint2*)gKhi : (uint2*)gVhi;

    float4 v = src[i];
    uint2 h;
    h.x = packh(v.x, v.y);
    h.y = packh(v.z, v.w);
    hi[i] = h;
}

// ================= main attention kernel =================
__global__ __launch_bounds__(NTHR, 3)
void fattn_mma_kernel(float* __restrict__ Og, const float* __restrict__ Qg)
{
    extern __shared__ __align__(1024) uint8_t smem[];
    const uint32_t sb = smem_u32(smem);

    const int tid  = threadIdx.x;
    const int w    = tid >> 5;           // 0..3
    const int lane = tid & 31;
    const int lr   = lane & 15;
    const int lc   = (lane >> 4) << 3;
    const int quad = lane & 3;

    const int qt = (gridDim.x - 1) - blockIdx.x;   // heavy tiles first
    const int bh = blockIdx.y;
    const size_t rowbase = (size_t)bh * SEQ;       // 128B-row index base

    const int n_kv = qt + 1;                       // kv tiles 0..qt (BM == BN)

    // hoisted swizzled address components:
    // swz(row*128 + col) == row*128 + (col ^ ((lr&7)<<4))  for col in [0,128)
    const uint32_t xorp = (uint32_t)((lr & 7) << 4);
    uint32_t rowoff[4], coloff[4];
    #pragma unroll
    for (int g = 0; g < 4; g++) {
        rowoff[g] = (uint32_t)((g * 16 + lr) * 128);
        coloff[g] = ((uint32_t)(g * 32 + lc * 2)) ^ xorp;
    }

    // tile issuer: one 16KB stage (KHI|VHI); 8 cp.async per thread
    auto issue_tile = [&](int kt, uint32_t stg) {
        const size_t tb = (rowbase + (size_t)kt * BN) * 128;
        const uint8_t* kh = gKhi + tb;
        const uint8_t* vh = gVhi + tb;
        #pragma unroll
        for (int j = 0; j < 4; j++) {
            uint32_t idx = (uint32_t)(tid + j * NTHR);
            uint32_t off = idx << 4;                 // 0..8176
            uint32_t so  = sb + stg + swz(off);
            cpa16(so + P_KHI, kh + off);
            cpa16(so + P_VHI, vh + off);
        }
        CP_COMMIT();
    };

    issue_tile(0, 0);                   // tile 0 -> stage 0

    // ---- Q: load fp32, scale, fp16 pack, stage in stage-3 region (8KB) ----
    // Stage 3 is first overwritten by issue(tile 3) at iter 0, after BAR(0) —
    // all warps have extracted their Q fragments by then.
    {
        const float* Qb = Qg + (rowbase + (size_t)qt * BM) * DH;
        #pragma unroll
        for (int it = 0; it < 8; it++) {
            int i  = tid + it * NTHR;   // 0..1023 float4
            int r  = i >> 4;
            int c4 = (i & 15) << 2;
            float4 v = *(const float4*)(Qb + r * DH + c4);
            uint2 h;
            h.x = packh(v.x * QSCALE, v.y * QSCALE);
            h.y = packh(v.z * QSCALE, v.w * QSCALE);
            *(uint2*)(smem + 3 * STAGE + swz((uint32_t)(r * 128 + c4 * 2))) = h;
        }
    }
    __syncthreads();

    uint32_t qh[4][4];
    #pragma unroll
    for (int ks = 0; ks < 4; ks++)
        ldsm4(qh[ks], sb + 3 * STAGE + rowoff[w] + coloff[ks]);

    // pre-issue tiles 1,2 into stages 1,2
    if (qt >= 1) issue_tile(1, STAGE);
    if (qt >= 2) issue_tile(2, 2 * STAGE);

    float o[8][4];
    #pragma unroll
    for (int n = 0; n < 8; n++)
        #pragma unroll
        for (int j = 0; j < 4; j++) o[n][j] = 0.f;
    float ol[4] = {0.f, 0.f, 0.f, 0.f};  // ones-column accum: row sums of P
    float m0 = -1e30f, m1 = -1e30f;

    const int qg0 = qt * BM + w * 16 + (lane >> 2);

    for (int kt = 0; kt < n_kv; kt++) {
        // exact tail-aware wait: pending-newer = min(qt-kt, 2)
        if (kt + 2 <= qt)      { CP_WAIT(2); }
        else if (kt + 1 <= qt) { CP_WAIT(1); }
        else                   { CP_WAIT(0); }
        __syncthreads();                 // single barrier: publish + WAR guard
        if (kt + 3 <= qt) issue_tile(kt + 3, (uint32_t)((kt + 3) & 3) * STAGE);

        const uint32_t stg = sb + (uint32_t)(kt & 3) * STAGE;

        // ---- S = Q.Khi  (single-pass fp16) ----
        float s[8][4];
        #pragma unroll
        for (int n = 0; n < 8; n++)
            #pragma unroll
            for (int j = 0; j < 4; j++) s[n][j] = 0.f;

        #pragma unroll
        for (int ks = 0; ks < 4; ks++) {
            #pragma unroll
            for (int kg = 0; kg < 4; kg++) {
                uint32_t bhf[4];
                ldsm4(bhf, stg + P_KHI + rowoff[kg] + coloff[ks]);
                mma_f16(s[2*kg],   qh[ks], bhf[0], bhf[2]);
                mma_f16(s[2*kg+1], qh[ks], bhf[1], bhf[3]);
            }
        }

        // ---- causal mask (diagonal tile only) ----
        if (kt == qt) {
            #pragma unroll
            for (int n = 0; n < 8; n++) {
                int kb = kt * BN + n * 8 + quad * 2;
                if (kb     > qg0)     s[n][0] = -30000.f;
                if (kb + 1 > qg0)     s[n][1] = -30000.f;
                if (kb     > qg0 + 8) s[n][2] = -30000.f;
                if (kb + 1 > qg0 + 8) s[n][3] = -30000.f;
            }
        }

        // ---- online softmax (log2 domain), packed fp16x2 max reduction ----
        float mx0 = s[0][0], mx1 = s[0][2];
        #pragma unroll
        for (int n = 0; n < 8; n++) {
            mx0 = fmaxf(mx0, fmaxf(s[n][0], s[n][1]));
            mx1 = fmaxf(mx1, fmaxf(s[n][2], s[n][3]));
        }
        // pack both row maxima; 2 shuffles reduce the quad for both rows at once.
        // fp16 rounding of the max is safe: all lanes agree on the same value,
        // and exp2(s - m) stays bounded (P <= ~1.004) — normalized out by ol.
        uint32_t mxp = packh(mx0, mx1);
        mxp = maxh2(mxp, __shfl_xor_sync(0xffffffffu, mxp, 1));
        mxp = maxh2(mxp, __shfl_xor_sync(0xffffffffu, mxp, 2));
        mx0 = h2lo_f32(mxp);
        mx1 = h2hi_f32(mxp);

        if (__any_sync(0xffffffffu, (mx0 > m0) || (mx1 > m1))) {
            float mn0 = fmaxf(m0, mx0), mn1 = fmaxf(m1, mx1);
            float a0 = ex2(m0 - mn0), a1 = ex2(m1 - mn1);
            m0 = mn0; m1 = mn1;
            #pragma unroll
            for (int n = 0; n < 8; n++) {
                o[n][0] *= a0; o[n][1] *= a0;
                o[n][2] *= a1; o[n][3] *= a1;
            }
            ol[0] *= a0; ol[1] *= a0;
            ol[2] *= a1; ol[3] *= a1;
        }

        // ---- P = exp2(s - m) computed directly in fp16x2 A-fragments ----
        uint32_t pa[4][4];
        #pragma unroll
        for (int j = 0; j < 4; j++) {
            pa[j][0] = ex2h2(packh(s[2*j][0]   - m0, s[2*j][1]   - m0));
            pa[j][1] = ex2h2(packh(s[2*j][2]   - m1, s[2*j][3]   - m1));
            pa[j][2] = ex2h2(packh(s[2*j+1][0] - m0, s[2*j+1][1] - m0));
            pa[j][3] = ex2h2(packh(s[2*j+1][2] - m1, s[2*j+1][3] - m1));
        }

        // ---- ol += P.1 first (no ldsm dependency -> tensor starts at once),
        //      then O += P.Vhi ----
        #pragma unroll
        for (int ks = 0; ks < 4; ks++) {
            mma_f16(ol, pa[ks], ONESH2, ONESH2);
            #pragma unroll
            for (int dg = 0; dg < 4; dg++) {
                uint32_t vhf[4];
                ldsm4t(vhf, stg + P_VHI + rowoff[ks] + coloff[dg]);
                mma_f16(o[2*dg],   pa[ks], vhf[0], vhf[1]);
                mma_f16(o[2*dg+1], pa[ks], vhf[2], vhf[3]);
            }
        }
    }

    // ---- epilogue: normalize by ones-column sums ----
    float inv0 = 1.0f / ol[0], inv1 = 1.0f / ol[2];
    float* Orow0 = Og + (rowbase + qg0) * DH;
    float* Orow1 = Orow0 + 8 * DH;
    #pragma unroll
    for (int n = 0; n < 8; n++) {
        int d = n * 8 + quad * 2;
        *(float2*)(Orow0 + d) = make_float2(o[n][0] * inv0, o[n][1] * inv0);
        *(float2*)(Orow1 + d) = make_float2(o[n][2] * inv1, o[n][3] * inv1);
    }
}

extern "C" void kernel_launch(void* const* d_in, const int* in_sizes, int n_in,
                              void* d_out, int out_size)
{
    const float* Q = (const float*)d_in[0];
    const float* K = (const float*)d_in[1];
    const float* V = (const float*)d_in[2];
    float* O = (float*)d_out;

    dim3 pgrid(NELEM / 4 / 256, 2);     // (4096, 2): K and V
    prep_kernel<<<pgrid, 256>>>(K, V);

    cudaFuncSetAttribute(fattn_mma_kernel,
                         cudaFuncAttributeMaxDynamicSharedMemorySize, SMEM_BYTES);
    dim3 grid(SEQ / BM, BHN);           // (32, 32)
    fattn_mma_kernel<<<grid, NTHR, SMEM_BYTES>>>(O, Q);
}

// round 16
// speedup vs baseline: 1.0720x; 1.0510x over previous
#include <cuda_runtime.h>
#include <cuda_fp16.h>
#include <cstdint>

// B=2,H=16,S=2048,D=64 causal attention, fp32 in/out.
#define BHN   32
#define SEQ   2048
#define DH    64
#define BM    64                        // q rows per CTA (4 warps x 16)
#define BN    64
#define NTHR  128
#define NELEM (BHN * SEQ * DH)          // 4,194,304

#define QSCALE 0.18033688f              // 0.125 * log2(e)
#define ONESH2 0x3C003C00u              // fp16x2 {1.0, 1.0}

// ---- pre-converted fp16 operands ----
__device__ __align__(16) uint8_t gKhi[NELEM * 2];
__device__ __align__(16) uint8_t gVhi[NELEM * 2];

// ---- smem: 4 stages x 16KB (KHI|VHI, 8KB each, XOR-swizzled) ----
#define STAGE   16384
#define P_KHI   0
#define P_VHI   8192
#define SMEM_BYTES (4 * STAGE)          // 65536 -> 3 CTAs/SM (192KB)

__device__ __forceinline__ uint32_t smem_u32(const void* p) {
    uint32_t a;
    asm("{ .reg .u64 t; cvta.to.shared.u64 t, %1; cvt.u32.u64 %0, t; }" : "=r"(a) : "l"(p));
    return a;
}
__device__ __forceinline__ uint32_t swz(uint32_t b) { return b ^ ((b >> 3) & 0x70u); }
__device__ __forceinline__ float ex2(float x) {
    float r; asm("ex2.approx.f32 %0, %1;" : "=f"(r) : "f"(x)); return r;
}
__device__ __forceinline__ uint32_t ex2h2(uint32_t x) {
    uint32_t r; asm("ex2.approx.f16x2 %0, %1;" : "=r"(r) : "r"(x)); return r;
}
__device__ __forceinline__ uint32_t maxh2(uint32_t a, uint32_t b) {
    uint32_t r; asm("max.f16x2 %0, %1, %2;" : "=r"(r) : "r"(a), "r"(b)); return r;
}
__device__ __forceinline__ float h2lo_f32(uint32_t h) {
    float r; asm("{ .reg .b16 x, y; mov.b32 {x, y}, %1; cvt.f32.f16 %0, x; }"
                 : "=f"(r) : "r"(h));
    return r;
}
__device__ __forceinline__ float h2hi_f32(uint32_t h) {
    float r; asm("{ .reg .b16 x, y; mov.b32 {x, y}, %1; cvt.f32.f16 %0, y; }"
                 : "=f"(r) : "r"(h));
    return r;
}
__device__ __forceinline__ void cpa16(uint32_t dst, const void* src) {
    asm volatile("cp.async.cg.shared.global [%0], [%1], 16;" :: "r"(dst), "l"(src));
}
#define CP_COMMIT() asm volatile("cp.async.commit_group;" ::: "memory")
#define CP_WAIT(n)  asm volatile("cp.async.wait_group %0;" :: "n"(n) : "memory")

__device__ __forceinline__ void ldsm4(uint32_t r[4], uint32_t addr) {
    asm volatile("ldmatrix.sync.aligned.m8n8.x4.shared.b16 {%0,%1,%2,%3}, [%4];"
        : "=r"(r[0]), "=r"(r[1]), "=r"(r[2]), "=r"(r[3]) : "r"(addr));
}
__device__ __forceinline__ void ldsm4t(uint32_t r[4], uint32_t addr) {
    asm volatile("ldmatrix.sync.aligned.m8n8.x4.trans.shared.b16 {%0,%1,%2,%3}, [%4];"
        : "=r"(r[0]), "=r"(r[1]), "=r"(r[2]), "=r"(r[3]) : "r"(addr));
}
// not volatile: lets ptxas schedule HMMA around FMA/MUFU chains
__device__ __forceinline__ void mma_f16(float c[4], const uint32_t a[4],
                                        uint32_t b0, uint32_t b1) {
    asm("mma.sync.aligned.m16n8k16.row.col.f32.f16.f16.f32 "
        "{%0,%1,%2,%3}, {%4,%5,%6,%7}, {%8,%9}, {%0,%1,%2,%3};"
        : "+f"(c[0]), "+f"(c[1]), "+f"(c[2]), "+f"(c[3])
        : "r"(a[0]), "r"(a[1]), "r"(a[2]), "r"(a[3]), "r"(b0), "r"(b1));
}
__device__ __forceinline__ uint32_t packh(float lo, float hi) {
    uint32_t r;
    asm("cvt.rn.f16x2.f32 %0, %1, %2;" : "=r"(r) : "f"(hi), "f"(lo));
    return r;
}

// ================= pre-pass: K,V fp32 -> fp16 =================
__global__ __launch_bounds__(256)
void prep_kernel(const float* __restrict__ Kg, const float* __restrict__ Vg)
{
    const int i = blockIdx.x * 256 + threadIdx.x;      // per float4
    const int t = blockIdx.y;                          // 0=K 1=V
    const float4* src = (t == 0) ? (const float4*)Kg : (const float4*)Vg;
    uint2* hi = (t == 0) ? (uint2*)gKhi : (uint2*)gVhi;

    float4 v = src[i];
    uint2 h;
    h.x = packh(v.x, v.y);
    h.y = packh(v.z, v.w);
    hi[i] = h;
}

// ================= main attention kernel =================
__global__ __launch_bounds__(NTHR, 3)
void fattn_mma_kernel(float* __restrict__ Og, const float* __restrict__ Qg)
{
    extern __shared__ __align__(1024) uint8_t smem[];
    const uint32_t sb = smem_u32(smem);

    const int tid  = threadIdx.x;
    const int w    = tid >> 5;           // 0..3
    const int lane = tid & 31;
    const int lr   = lane & 15;
    const int lc   = (lane >> 4) << 3;
    const int quad = lane & 3;

    const int qt = (gridDim.x - 1) - blockIdx.x;   // heavy tiles first
    const int bh = blockIdx.y;
    const size_t rowbase = (size_t)bh * SEQ;       // 128B-row index base

    // hoisted swizzled address components:
    // swz(row*128 + col) == row*128 + (col ^ ((lr&7)<<4))  for col in [0,128)
    const uint32_t xorp = (uint32_t)((lr & 7) << 4);
    uint32_t rowoff[4], coloff[4];
    #pragma unroll
    for (int g = 0; g < 4; g++) {
        rowoff[g] = (uint32_t)((g * 16 + lr) * 128);
        coloff[g] = ((uint32_t)(g * 32 + lc * 2)) ^ xorp;
    }

    // paired tile issuer: tiles t0 (and t0+1 if two) in ONE commit group
    auto issue_pair = [&](int t0, bool two) {
        const uint8_t* kh0 = gKhi + (rowbase + (size_t)t0 * BN) * 128;
        const uint8_t* vh0 = gVhi + (rowbase + (size_t)t0 * BN) * 128;
        const uint32_t stg0 = sb + (uint32_t)(t0 & 3) * STAGE;
        #pragma unroll
        for (int j = 0; j < 4; j++) {
            uint32_t off = ((uint32_t)(tid + j * NTHR)) << 4;
            uint32_t so  = stg0 + swz(off);
            cpa16(so + P_KHI, kh0 + off);
            cpa16(so + P_VHI, vh0 + off);
        }
        if (two) {
            const uint8_t* kh1 = kh0 + (size_t)BN * 128;
            const uint8_t* vh1 = vh0 + (size_t)BN * 128;
            const uint32_t stg1 = sb + (uint32_t)((t0 + 1) & 3) * STAGE;
            #pragma unroll
            for (int j = 0; j < 4; j++) {
                uint32_t off = ((uint32_t)(tid + j * NTHR)) << 4;
                uint32_t so  = stg1 + swz(off);
                cpa16(so + P_KHI, kh1 + off);
                cpa16(so + P_VHI, vh1 + off);
            }
        }
        CP_COMMIT();
    };

    issue_pair(0, qt >= 1);             // tiles 0(,1) -> stages 0(,1)

    // ---- Q: load fp32, scale, fp16 pack, stage in stage-2 region (8KB) ----
    // Stage 2 is first overwritten by issue of tile 2 inside the loop, which
    // happens after the loop's barrier — all warps extracted Q frags by then.
    {
        const float* Qb = Qg + (rowbase + (size_t)qt * BM) * DH;
        #pragma unroll
        for (int it = 0; it < 8; it++) {
            int i  = tid + it * NTHR;   // 0..1023 float4
            int r  = i >> 4;
            int c4 = (i & 15) << 2;
            float4 v = *(const float4*)(Qb + r * DH + c4);
            uint2 h;
            h.x = packh(v.x * QSCALE, v.y * QSCALE);
            h.y = packh(v.z * QSCALE, v.w * QSCALE);
            *(uint2*)(smem + 2 * STAGE + swz((uint32_t)(r * 128 + c4 * 2))) = h;
        }
    }
    __syncthreads();

    uint32_t qh[4][4];
    #pragma unroll
    for (int ks = 0; ks < 4; ks++)
        ldsm4(qh[ks], sb + 2 * STAGE + rowoff[w] + coloff[ks]);

    float o[8][4];
    #pragma unroll
    for (int n = 0; n < 8; n++)
        #pragma unroll
        for (int j = 0; j < 4; j++) o[n][j] = 0.f;
    float ol[4] = {0.f, 0.f, 0.f, 0.f};  // ones-column accum: row sums of P
    float m0 = -1e30f, m1 = -1e30f;

    const int qg0 = qt * BM + w * 16 + (lane >> 2);

    // ---- helpers ----
    auto sgemm = [&](float s[8][4], uint32_t stg) {
        #pragma unroll
        for (int n = 0; n < 8; n++)
            #pragma unroll
            for (int j = 0; j < 4; j++) s[n][j] = 0.f;
        #pragma unroll
        for (int ks = 0; ks < 4; ks++) {
            #pragma unroll
            for (int kg = 0; kg < 4; kg++) {
                uint32_t bhf[4];
                ldsm4(bhf, stg + P_KHI + rowoff[kg] + coloff[ks]);
                mma_f16(s[2*kg],   qh[ks], bhf[0], bhf[2]);
                mma_f16(s[2*kg+1], qh[ks], bhf[1], bhf[3]);
            }
        }
    };
    auto maskdiag = [&](float s[8][4]) {       // tile == qt
        #pragma unroll
        for (int n = 0; n < 8; n++) {
            int kb = qt * BN + n * 8 + quad * 2;
            if (kb     > qg0)     s[n][0] = -30000.f;
            if (kb + 1 > qg0)     s[n][1] = -30000.f;
            if (kb     > qg0 + 8) s[n][2] = -30000.f;
            if (kb + 1 > qg0 + 8) s[n][3] = -30000.f;
        }
    };
    auto rescale_if_needed = [&](float mx0, float mx1) {
        if (__any_sync(0xffffffffu, (mx0 > m0) || (mx1 > m1))) {
            float mn0 = fmaxf(m0, mx0), mn1 = fmaxf(m1, mx1);
            float a0 = ex2(m0 - mn0), a1 = ex2(m1 - mn1);
            m0 = mn0; m1 = mn1;
            #pragma unroll
            for (int n = 0; n < 8; n++) {
                o[n][0] *= a0; o[n][1] *= a0;
                o[n][2] *= a1; o[n][3] *= a1;
            }
            ol[0] *= a0; ol[1] *= a0;
            ol[2] *= a1; ol[3] *= a1;
        }
    };
    auto pv = [&](const float s[8][4], uint32_t stg) {
        uint32_t pa[4][4];
        #pragma unroll
        for (int j = 0; j < 4; j++) {
            pa[j][0] = ex2h2(packh(s[2*j][0]   - m0, s[2*j][1]   - m0));
            pa[j][1] = ex2h2(packh(s[2*j][2]   - m1, s[2*j][3]   - m1));
            pa[j][2] = ex2h2(packh(s[2*j+1][0] - m0, s[2*j+1][1] - m0));
            pa[j][3] = ex2h2(packh(s[2*j+1][2] - m1, s[2*j+1][3] - m1));
        }
        #pragma unroll
        for (int ks = 0; ks < 4; ks++) {
            mma_f16(ol, pa[ks], ONESH2, ONESH2);
            #pragma unroll
            for (int dg = 0; dg < 4; dg++) {
                uint32_t vhf[4];
                ldsm4t(vhf, stg + P_VHI + rowoff[ks] + coloff[dg]);
                mma_f16(o[2*dg],   pa[ks], vhf[0], vhf[1]);
                mma_f16(o[2*dg+1], pa[ks], vhf[2], vhf[3]);
            }
        }
    };

    // ---- main loop: two kv tiles per iteration, one joint softmax ----
    for (int kt = 0; kt + 1 <= qt; kt += 2) {
        CP_WAIT(0);                      // tiles kt, kt+1 resident
        __syncthreads();                 // publish + WAR guard
        if (kt + 2 <= qt) issue_pair(kt + 2, kt + 3 <= qt);

        const uint32_t stgA = sb + (uint32_t)(kt & 3) * STAGE;
        const uint32_t stgB = sb + (uint32_t)((kt + 1) & 3) * STAGE;

        float sA[8][4], sB[8][4];
        sgemm(sA, stgA);
        sgemm(sB, stgB);
        if (kt + 1 == qt) maskdiag(sB);  // A (=kt) is never the diagonal here

        // joint max over both tiles (128 keys)
        float mx0 = sA[0][0], mx1 = sA[0][2];
        #pragma unroll
        for (int n = 0; n < 8; n++) {
            mx0 = fmaxf(mx0, fmaxf(fmaxf(sA[n][0], sA[n][1]), fmaxf(sB[n][0], sB[n][1])));
            mx1 = fmaxf(mx1, fmaxf(fmaxf(sA[n][2], sA[n][3]), fmaxf(sB[n][2], sB[n][3])));
        }
        uint32_t mxp = packh(mx0, mx1);
        mxp = maxh2(mxp, __shfl_xor_sync(0xffffffffu, mxp, 1));
        mxp = maxh2(mxp, __shfl_xor_sync(0xffffffffu, mxp, 2));
        rescale_if_needed(h2lo_f32(mxp), h2hi_f32(mxp));

        pv(sA, stgA);
        pv(sB, stgB);
    }

    // ---- tail: single tile (qt even, including qt == 0) ----
    if ((qt & 1) == 0) {
        CP_WAIT(0);
        __syncthreads();
        const uint32_t stg = sb + (uint32_t)(qt & 3) * STAGE;
        float sA[8][4];
        sgemm(sA, stg);
        maskdiag(sA);

        float mx0 = sA[0][0], mx1 = sA[0][2];
        #pragma unroll
        for (int n = 0; n < 8; n++) {
            mx0 = fmaxf(mx0, fmaxf(sA[n][0], sA[n][1]));
            mx1 = fmaxf(mx1, fmaxf(sA[n][2], sA[n][3]));
        }
        uint32_t mxp = packh(mx0, mx1);
        mxp = maxh2(mxp, __shfl_xor_sync(0xffffffffu, mxp, 1));
        mxp = maxh2(mxp, __shfl_xor_sync(0xffffffffu, mxp, 2));
        rescale_if_needed(h2lo_f32(mxp), h2hi_f32(mxp));

        pv(sA, stg);
    }

    // ---- epilogue: normalize by ones-column sums ----
    float inv0 = 1.0f / ol[0], inv1 = 1.0f / ol[2];
    float* Orow0 = Og + (rowbase + qg0) * DH;
    float* Orow1 = Orow0 + 8 * DH;
    #pragma unroll
    for (int n = 0; n < 8; n++) {
        int d = n * 8 + quad * 2;
        *(float2*)(Orow0 + d) = make_float2(o[n][0] * inv0, o[n][1] * inv0);
        *(float2*)(Orow1 + d) = make_float2(o[n][2] * inv1, o[n][3] * inv1);
    }
}

extern "C" void kernel_launch(void* const* d_in, const int* in_sizes, int n_in,
                              void* d_out, int out_size)
{
    const float* Q = (const float*)d_in[0];
    const float* K = (const float*)d_in[1];
    const float* V = (const float*)d_in[2];
    float* O = (float*)d_out;

    dim3 pgrid(NELEM / 4 / 256, 2);     // (4096, 2): K and V
    prep_kernel<<<pgrid, 256>>>(K, V);

    cudaFuncSetAttribute(fattn_mma_kernel,
                         cudaFuncAttributeMaxDynamicSharedMemorySize, SMEM_BYTES);
    dim3 grid(SEQ / BM, BHN);           // (32, 32)
    fattn_mma_kernel<<<grid, NTHR, SMEM_BYTES>>>(O, Q);
}